// round 2
// baseline (speedup 1.0000x reference)
#include <cuda_runtime.h>

#define NN 100000
#define NE 1600000
#define F 128
#define EDIM 16
#define NCLS 16
#define SLOPE 0.2f

// ---------------- scratch (device globals; no allocation allowed) ----------------
__device__ __align__(16) float g_xl[(size_t)NN * F];    // GEMM output / gather source
__device__ __align__(16) float g_buf[(size_t)NN * F];   // layer output (relu'd)
__device__ float g_as[NN];
__device__ float g_ad[NN];
__device__ float g_alphaSelf[NN];
__device__ float g_ae0[NE];
__device__ float g_ae1[NE];
__device__ float g_sum0[NN];
__device__ float g_sum1[NN];
__device__ int   g_degi[NN];
__device__ float g_aeL0[NN];
__device__ float g_aeL1[NN];
__device__ int   g_off[NN + 1];
__device__ int   g_cursor[NN];
__device__ int   g_csr_src[NE];
__device__ int   g_csr_eid[NE];
__device__ __align__(16) float g_we0[EDIM];
__device__ __align__(16) float g_we1[EDIM];

static inline int cdiv(int a, int b) { return (a + b - 1) / b; }

// ---------------- w_e = We @ a_e (two 16x128 @ 128 matvecs) ----------------
__global__ void k_we(const float* __restrict__ We0, const float* __restrict__ ae0v,
                     const float* __restrict__ We1, const float* __restrict__ ae1v) {
    int t = threadIdx.x;
    if (t < EDIM) {
        float s = 0.f;
        for (int k = 0; k < F; k++) s += We0[t * F + k] * ae0v[k];
        g_we0[t] = s;
    } else if (t < 2 * EDIM) {
        int j = t - EDIM;
        float s = 0.f;
        for (int k = 0; k < F; k++) s += We1[j * F + k] * ae1v[k];
        g_we1[j] = s;
    }
}

__global__ void k_zero(int n) {
    int i = blockIdx.x * blockDim.x + threadIdx.x;
    if (i < n) { g_sum0[i] = 0.f; g_sum1[i] = 0.f; g_degi[i] = 0; }
}

// ---------------- per-edge: ae = dot(edge_attr, w_e); segment sums; degree ----------------
__global__ void k_edge_pre(const float* __restrict__ ea, const int* __restrict__ ei, int e) {
    int i = blockIdx.x * blockDim.x + threadIdx.x;
    if (i >= e) return;
    int dst = ei[e + i];
    const float4* v = (const float4*)(ea + (size_t)i * EDIM);
    const float4* w0 = (const float4*)g_we0;
    const float4* w1 = (const float4*)g_we1;
    float a0 = 0.f, a1 = 0.f;
#pragma unroll
    for (int q = 0; q < 4; q++) {
        float4 t = v[q];
        float4 u0 = w0[q], u1 = w1[q];
        a0 += t.x * u0.x + t.y * u0.y + t.z * u0.z + t.w * u0.w;
        a1 += t.x * u1.x + t.y * u1.y + t.z * u1.z + t.w * u1.w;
    }
    g_ae0[i] = a0;
    g_ae1[i] = a1;
    atomicAdd(&g_sum0[dst], a0);
    atomicAdd(&g_sum1[dst], a1);
    atomicAdd(&g_degi[dst], 1);
}

// self-loop edge alpha: mean(ea)·w_e = segsum(ea·w_e)/max(deg,1)
__global__ void k_node_pre(int n) {
    int i = blockIdx.x * blockDim.x + threadIdx.x;
    if (i >= n) return;
    float d = (float)(g_degi[i] > 0 ? g_degi[i] : 1);
    g_aeL0[i] = g_sum0[i] / d;
    g_aeL1[i] = g_sum1[i] / d;
}

// ---------------- single-block exclusive scan of degrees -> CSR offsets ----------------
__global__ void k_scan(int n) {
    __shared__ int warp_sums[32];
    __shared__ int s_carry;
    int tid = threadIdx.x;           // 1024
    int lane = tid & 31, wid = tid >> 5;
    if (tid == 0) s_carry = 0;
    __syncthreads();
    for (int base = 0; base < n; base += 1024) {
        int i = base + tid;
        int v = (i < n) ? g_degi[i] : 0;
        int x = v;
#pragma unroll
        for (int d = 1; d < 32; d <<= 1) {
            int y = __shfl_up_sync(0xffffffffu, x, d);
            if (lane >= d) x += y;
        }
        if (lane == 31) warp_sums[wid] = x;
        __syncthreads();
        if (tid < 32) {
            int w = warp_sums[tid];
#pragma unroll
            for (int d = 1; d < 32; d <<= 1) {
                int y = __shfl_up_sync(0xffffffffu, w, d);
                if (tid >= d) w += y;
            }
            warp_sums[tid] = w;
        }
        __syncthreads();
        int carry = s_carry;
        int woff = wid ? warp_sums[wid - 1] : 0;
        int excl = carry + woff + x - v;
        if (i < n) { g_off[i] = excl; g_cursor[i] = excl; }
        int total = warp_sums[31];
        __syncthreads();
        if (tid == 0) s_carry = carry + total;
        __syncthreads();
    }
    if (threadIdx.x == 0) g_off[n] = s_carry;
}

__global__ void k_csr_fill(const int* __restrict__ ei, int e) {
    int i = blockIdx.x * blockDim.x + threadIdx.x;
    if (i >= e) return;
    int src = ei[i];
    int dst = ei[e + i];
    int pos = atomicAdd(&g_cursor[dst], 1);
    g_csr_src[pos] = src;
    g_csr_eid[pos] = i;
}

// ---------------- fp32 GEMM: C[n,128] = A[n,128] @ B[128,128] (+bias, relu) ----------------
// BM=64, BN=128, BK=16, 128 threads, 8x8 register tile. A==nullptr -> read g_buf. C = g_xl.
__global__ void k_gemm(const float* __restrict__ A_in, const float* __restrict__ B,
                       const float* __restrict__ bias, int nrows, int relu) {
    const float* A = A_in ? A_in : g_buf;
    __shared__ __align__(16) float As[16][64];
    __shared__ __align__(16) float Bs[16][128];
    int tid = threadIdx.x;
    int tx = tid & 15;   // col group: cols tx*8..tx*8+7
    int ty = tid >> 4;   // row group: rows ty*8..ty*8+7
    int r0 = blockIdx.x * 64;
    float acc[8][8];
#pragma unroll
    for (int r = 0; r < 8; r++)
#pragma unroll
        for (int c = 0; c < 8; c++) acc[r][c] = 0.f;

    for (int k0 = 0; k0 < 128; k0 += 16) {
        // load A tile (64 x 16), transposed into As[k][m]
#pragma unroll
        for (int j = 0; j < 2; j++) {
            int f4 = tid * 2 + j;      // 0..255
            int row = f4 >> 2;         // 0..63
            int kq = (f4 & 3) * 4;     // 0,4,8,12
            int gr = r0 + row;
            if (gr >= nrows) gr = nrows - 1;
            float4 t = *(const float4*)(A + (size_t)gr * F + k0 + kq);
            As[kq + 0][row] = t.x; As[kq + 1][row] = t.y;
            As[kq + 2][row] = t.z; As[kq + 3][row] = t.w;
        }
        // load B tile (16 x 128)
#pragma unroll
        for (int j = 0; j < 4; j++) {
            int f4 = tid * 4 + j;      // 0..511
            int row = f4 >> 5;         // 0..15
            int c4 = (f4 & 31) * 4;
            *(float4*)(&Bs[row][c4]) = *(const float4*)(B + (size_t)(k0 + row) * F + c4);
        }
        __syncthreads();
#pragma unroll
        for (int kk = 0; kk < 16; kk++) {
            float ra[8], rb[8];
            *(float4*)(ra)     = *(const float4*)(&As[kk][ty * 8]);
            *(float4*)(ra + 4) = *(const float4*)(&As[kk][ty * 8 + 4]);
            *(float4*)(rb)     = *(const float4*)(&Bs[kk][tx * 8]);
            *(float4*)(rb + 4) = *(const float4*)(&Bs[kk][tx * 8 + 4]);
#pragma unroll
            for (int r = 0; r < 8; r++)
#pragma unroll
                for (int c = 0; c < 8; c++) acc[r][c] += ra[r] * rb[c];
        }
        __syncthreads();
    }
    // epilogue
#pragma unroll
    for (int r = 0; r < 8; r++) {
        int gr = r0 + ty * 8 + r;
        if (gr < nrows) {
            float o[8];
#pragma unroll
            for (int c = 0; c < 8; c++) {
                float v = acc[r][c];
                if (bias) v += bias[tx * 8 + c];
                if (relu) v = fmaxf(v, 0.f);
                o[c] = v;
            }
            *(float4*)(g_xl + (size_t)gr * F + tx * 8)     = *(float4*)(o);
            *(float4*)(g_xl + (size_t)gr * F + tx * 8 + 4) = *(float4*)(o + 4);
        }
    }
}

// ---------------- per-node attention scalars: as = xl·a_s, ad = xl·a_d, self alpha ----------------
__global__ void k_dots(const float* __restrict__ a_s, const float* __restrict__ a_d,
                       int layer, int n) {
    int g = blockIdx.x * blockDim.x + threadIdx.x;
    int node = g >> 5;
    int lane = g & 31;
    if (node >= n) return;
    float4 x = *(const float4*)(g_xl + (size_t)node * F + lane * 4);
    float4 s4 = *(const float4*)(a_s + lane * 4);
    float4 d4 = *(const float4*)(a_d + lane * 4);
    float ps = x.x * s4.x + x.y * s4.y + x.z * s4.z + x.w * s4.w;
    float pd = x.x * d4.x + x.y * d4.y + x.z * d4.z + x.w * d4.w;
#pragma unroll
    for (int o = 16; o; o >>= 1) {
        ps += __shfl_xor_sync(0xffffffffu, ps, o);
        pd += __shfl_xor_sync(0xffffffffu, pd, o);
    }
    if (lane == 0) {
        g_as[node] = ps;
        g_ad[node] = pd;
        float aeL = layer ? g_aeL1[node] : g_aeL0[node];
        float a = ps + pd + aeL;
        g_alphaSelf[node] = a > 0.f ? a : SLOPE * a;
    }
}

// ---------------- per-node softmax + weighted aggregation (CSR, no atomics) ----------------
__global__ void k_agg(const float* __restrict__ bias, int layer, int n) {
    int v = blockIdx.x;
    int tid = threadIdx.x;  // 128
    const float* ae = layer ? g_ae1 : g_ae0;
    __shared__ float red[4];
    __shared__ float s_m, s_sum;
    int s = g_off[v], e = g_off[v + 1];
    float adv = g_ad[v];
    float aself = g_alphaSelf[v];

    // pass 1: max
    float m = aself;
    for (int i = s + tid; i < e; i += 128) {
        float a = g_as[g_csr_src[i]] + adv + ae[g_csr_eid[i]];
        a = a > 0.f ? a : SLOPE * a;
        m = fmaxf(m, a);
    }
#pragma unroll
    for (int o = 16; o; o >>= 1) m = fmaxf(m, __shfl_xor_sync(0xffffffffu, m, o));
    if ((tid & 31) == 0) red[tid >> 5] = m;
    __syncthreads();
    if (tid == 0) s_m = fmaxf(fmaxf(red[0], red[1]), fmaxf(red[2], red[3]));
    __syncthreads();
    m = s_m;

    // pass 2: sum of exp
    float p = 0.f;
    for (int i = s + tid; i < e; i += 128) {
        float a = g_as[g_csr_src[i]] + adv + ae[g_csr_eid[i]];
        a = a > 0.f ? a : SLOPE * a;
        p += __expf(a - m);
    }
#pragma unroll
    for (int o = 16; o; o >>= 1) p += __shfl_xor_sync(0xffffffffu, p, o);
    if ((tid & 31) == 0) red[tid >> 5] = p;
    __syncthreads();
    if (tid == 0) s_sum = red[0] + red[1] + red[2] + red[3] + __expf(aself - m);
    __syncthreads();
    float rinv = 1.0f / s_sum;

    // pass 3: weighted gather (serial over edges; 128 threads = feature dim)
    float acc = __expf(aself - m) * rinv * g_xl[(size_t)v * F + tid];
    for (int i = s; i < e; i++) {
        int u = g_csr_src[i];
        float a = g_as[u] + adv + ae[g_csr_eid[i]];
        a = a > 0.f ? a : SLOPE * a;
        float w = __expf(a - m) * rinv;
        acc += w * g_xl[(size_t)u * F + tid];
    }
    g_buf[(size_t)v * F + tid] = fmaxf(acc + bias[tid], 0.f);
}

// ---------------- head: logits = p @ W2 + b2; log_softmax over 16 classes ----------------
__global__ void k_head(const float* __restrict__ W2, const float* __restrict__ b2,
                       float* __restrict__ out, int n) {
    __shared__ float sW[F * NCLS];
    int tid = threadIdx.x;  // 256
    for (int i = tid; i < F * NCLS; i += 256) sW[i] = W2[i];
    __syncthreads();
    int r = tid >> 4, c = tid & 15;
    int node = blockIdx.x * 16 + r;
    bool valid = node < n;
    int nc = valid ? node : (n - 1);
    const float* pr = g_xl + (size_t)nc * F;
    float acc = b2[c];
#pragma unroll 8
    for (int k = 0; k < F; k++) acc += pr[k] * sW[k * NCLS + c];
    // log-softmax across the 16-thread class group (group-aligned within warp)
    float mm = acc;
#pragma unroll
    for (int o = 8; o; o >>= 1) mm = fmaxf(mm, __shfl_xor_sync(0xffffffffu, mm, o));
    float ex = __expf(acc - mm);
    float ssum = ex;
#pragma unroll
    for (int o = 8; o; o >>= 1) ssum += __shfl_xor_sync(0xffffffffu, ssum, o);
    if (valid) out[(size_t)node * NCLS + c] = acc - mm - logf(ssum);
}

// ---------------- driver ----------------
extern "C" void kernel_launch(void* const* d_in, const int* in_sizes, int n_in,
                              void* d_out, int out_size) {
    const float* x      = (const float*)d_in[0];
    const float* ea     = (const float*)d_in[1];
    const float* W0     = (const float*)d_in[2];
    const float* a_src0 = (const float*)d_in[3];
    const float* a_dst0 = (const float*)d_in[4];
    const float* We0    = (const float*)d_in[5];
    const float* a_e0   = (const float*)d_in[6];
    const float* b0     = (const float*)d_in[7];
    const float* W1     = (const float*)d_in[8];
    const float* a_src1 = (const float*)d_in[9];
    const float* a_dst1 = (const float*)d_in[10];
    const float* We1    = (const float*)d_in[11];
    const float* a_e1   = (const float*)d_in[12];
    const float* b1     = (const float*)d_in[13];
    const float* lin1_w = (const float*)d_in[14];
    const float* lin1_b = (const float*)d_in[15];
    const float* lin2_w = (const float*)d_in[16];
    const float* lin2_b = (const float*)d_in[17];
    const int*   ei     = (const int*)d_in[18];   // JAX default x64-disabled -> int32

    int n = in_sizes[0] / F;
    int e = in_sizes[1] / EDIM;
    float* out = (float*)d_out;

    // preprocessing (edge attention scalars + CSR), shared by both layers
    k_we<<<1, 32>>>(We0, a_e0, We1, a_e1);
    k_zero<<<cdiv(n, 256), 256>>>(n);
    k_edge_pre<<<cdiv(e, 256), 256>>>(ea, ei, e);
    k_node_pre<<<cdiv(n, 256), 256>>>(n);
    k_scan<<<1, 1024>>>(n);
    k_csr_fill<<<cdiv(e, 256), 256>>>(ei, e);

    // GAT layer 0
    k_gemm<<<cdiv(n, 64), 128>>>(x, W0, nullptr, n, 0);
    k_dots<<<cdiv(n * 32, 256), 256>>>(a_src0, a_dst0, 0, n);
    k_agg<<<n, 128>>>(b0, 0, n);

    // GAT layer 1
    k_gemm<<<cdiv(n, 64), 128>>>(nullptr, W1, nullptr, n, 0);
    k_dots<<<cdiv(n * 32, 256), 256>>>(a_src1, a_dst1, 1, n);
    k_agg<<<n, 128>>>(b1, 1, n);

    // MLP head
    k_gemm<<<cdiv(n, 64), 128>>>(nullptr, lin1_w, lin1_b, n, 1);
    k_head<<<cdiv(n, 16), 256>>>(lin2_w, lin2_b, out, n);
}

// round 3
// speedup vs baseline: 1.6231x; 1.6231x over previous
#include <cuda_runtime.h>

#define NN 100000
#define NE 1600000
#define F 128
#define EDIM 16
#define NCLS 16
#define SLOPE 0.2f
#define SB 512

// ---------------- scratch (device globals; no allocation allowed) ----------------
__device__ __align__(16) float g_xl[(size_t)NN * F];    // GEMM output / gather source
__device__ __align__(16) float g_buf[(size_t)NN * F];   // layer output (relu'd)
__device__ float g_as[NN];
__device__ float g_ad[NN];
__device__ float g_alphaSelf[NN];
__device__ float g_ae0[NE];
__device__ float g_ae1[NE];
__device__ float g_sum0[NN];
__device__ float g_sum1[NN];
__device__ int   g_degi[NN];
__device__ float g_aeL0[NN];
__device__ float g_aeL1[NN];
__device__ int   g_off[NN + 1];
__device__ int   g_cursor[NN];
__device__ int   g_csr_src[NE];
__device__ float g_csr_ae0[NE];   // edge alpha term, CSR order (no eid indirection)
__device__ float g_csr_ae1[NE];
__device__ int   g_bsum[1024];
__device__ __align__(16) float g_we0[EDIM];
__device__ __align__(16) float g_we1[EDIM];

static inline int cdiv(int a, int b) { return (a + b - 1) / b; }

// ---------------- w_e = We @ a_e (two 16x128 @ 128 matvecs) ----------------
__global__ void k_we(const float* __restrict__ We0, const float* __restrict__ ae0v,
                     const float* __restrict__ We1, const float* __restrict__ ae1v) {
    int t = threadIdx.x;
    if (t < EDIM) {
        float s = 0.f;
        for (int k = 0; k < F; k++) s += We0[t * F + k] * ae0v[k];
        g_we0[t] = s;
    } else if (t < 2 * EDIM) {
        int j = t - EDIM;
        float s = 0.f;
        for (int k = 0; k < F; k++) s += We1[j * F + k] * ae1v[k];
        g_we1[j] = s;
    }
}

__global__ void k_zero(int n) {
    int i = blockIdx.x * blockDim.x + threadIdx.x;
    if (i < n) { g_sum0[i] = 0.f; g_sum1[i] = 0.f; g_degi[i] = 0; }
}

// ---------------- per-edge: ae = dot(edge_attr, w_e); segment sums; degree ----------------
__global__ void k_edge_pre(const float* __restrict__ ea, const int* __restrict__ ei, int e) {
    int i = blockIdx.x * blockDim.x + threadIdx.x;
    if (i >= e) return;
    int dst = ei[e + i];
    const float4* v = (const float4*)(ea + (size_t)i * EDIM);
    const float4* w0 = (const float4*)g_we0;
    const float4* w1 = (const float4*)g_we1;
    float a0 = 0.f, a1 = 0.f;
#pragma unroll
    for (int q = 0; q < 4; q++) {
        float4 t = v[q];
        float4 u0 = w0[q], u1 = w1[q];
        a0 += t.x * u0.x + t.y * u0.y + t.z * u0.z + t.w * u0.w;
        a1 += t.x * u1.x + t.y * u1.y + t.z * u1.z + t.w * u1.w;
    }
    g_ae0[i] = a0;
    g_ae1[i] = a1;
    atomicAdd(&g_sum0[dst], a0);
    atomicAdd(&g_sum1[dst], a1);
    atomicAdd(&g_degi[dst], 1);
}

// self-loop edge alpha: mean(ea)·w_e = segsum(ea·w_e)/max(deg,1)
__global__ void k_node_pre(int n) {
    int i = blockIdx.x * blockDim.x + threadIdx.x;
    if (i >= n) return;
    float d = (float)(g_degi[i] > 0 ? g_degi[i] : 1);
    g_aeL0[i] = g_sum0[i] / d;
    g_aeL1[i] = g_sum1[i] / d;
}

// ---------------- multi-block exclusive scan of degrees -> CSR offsets ----------------
__global__ void k_scan1(int n) {
    __shared__ int wsum[16];
    int tid = threadIdx.x;            // 512
    int i = blockIdx.x * SB + tid;
    int lane = tid & 31, wid = tid >> 5;
    int v = (i < n) ? g_degi[i] : 0;
    int x = v;
#pragma unroll
    for (int d = 1; d < 32; d <<= 1) {
        int y = __shfl_up_sync(0xffffffffu, x, d);
        if (lane >= d) x += y;
    }
    if (lane == 31) wsum[wid] = x;
    __syncthreads();
    if (tid < 16) {
        int w = wsum[tid];
#pragma unroll
        for (int d = 1; d < 16; d <<= 1) {
            int y = __shfl_up_sync(0x0000ffffu, w, d);
            if (tid >= d) w += y;
        }
        wsum[tid] = w;
    }
    __syncthreads();
    int excl = (wid ? wsum[wid - 1] : 0) + x - v;
    if (i < n) g_off[i] = excl;
    if (tid == SB - 1) g_bsum[blockIdx.x] = wsum[15];
}

__global__ void k_scan2(int nb) {
    __shared__ int wsum[32];
    int tid = threadIdx.x;            // 1024
    int lane = tid & 31, wid = tid >> 5;
    int v = (tid < nb) ? g_bsum[tid] : 0;
    int x = v;
#pragma unroll
    for (int d = 1; d < 32; d <<= 1) {
        int y = __shfl_up_sync(0xffffffffu, x, d);
        if (lane >= d) x += y;
    }
    if (lane == 31) wsum[wid] = x;
    __syncthreads();
    if (tid < 32) {
        int w = wsum[tid];
#pragma unroll
        for (int d = 1; d < 32; d <<= 1) {
            int y = __shfl_up_sync(0xffffffffu, w, d);
            if (tid >= d) w += y;
        }
        wsum[tid] = w;
    }
    __syncthreads();
    int excl = (wid ? wsum[wid - 1] : 0) + x - v;
    if (tid < nb) g_bsum[tid] = excl;
}

__global__ void k_scan3(int n) {
    int i = blockIdx.x * SB + threadIdx.x;
    if (i >= n) return;
    int o = g_off[i] + g_bsum[i / SB];
    g_off[i] = o;
    g_cursor[i] = o;
    if (i == n - 1) g_off[n] = o + g_degi[i];
}

__global__ void k_csr_fill(const int* __restrict__ ei, int e) {
    int i = blockIdx.x * blockDim.x + threadIdx.x;
    if (i >= e) return;
    int src = ei[i];
    int dst = ei[e + i];
    int pos = atomicAdd(&g_cursor[dst], 1);
    g_csr_src[pos] = src;
    g_csr_ae0[pos] = g_ae0[i];
    g_csr_ae1[pos] = g_ae1[i];
}

// ---------------- fp32 GEMM: C[n,128] = A[n,128] @ B[128,128] (+bias, relu) ----------------
// BM=64, BN=128, BK=16, 128 threads, 8x8 register tile. A==nullptr -> read g_buf. C = g_xl.
__global__ void k_gemm(const float* __restrict__ A_in, const float* __restrict__ B,
                       const float* __restrict__ bias, int nrows, int relu) {
    const float* A = A_in ? A_in : g_buf;
    __shared__ __align__(16) float As[16][64];
    __shared__ __align__(16) float Bs[16][128];
    int tid = threadIdx.x;
    int tx = tid & 15;   // col group: cols tx*8..tx*8+7
    int ty = tid >> 4;   // row group: rows ty*8..ty*8+7
    int r0 = blockIdx.x * 64;
    float acc[8][8];
#pragma unroll
    for (int r = 0; r < 8; r++)
#pragma unroll
        for (int c = 0; c < 8; c++) acc[r][c] = 0.f;

    for (int k0 = 0; k0 < 128; k0 += 16) {
#pragma unroll
        for (int j = 0; j < 2; j++) {
            int f4 = tid * 2 + j;      // 0..255
            int row = f4 >> 2;         // 0..63
            int kq = (f4 & 3) * 4;     // 0,4,8,12
            int gr = r0 + row;
            if (gr >= nrows) gr = nrows - 1;
            float4 t = *(const float4*)(A + (size_t)gr * F + k0 + kq);
            As[kq + 0][row] = t.x; As[kq + 1][row] = t.y;
            As[kq + 2][row] = t.z; As[kq + 3][row] = t.w;
        }
#pragma unroll
        for (int j = 0; j < 4; j++) {
            int f4 = tid * 4 + j;      // 0..511
            int row = f4 >> 5;         // 0..15
            int c4 = (f4 & 31) * 4;
            *(float4*)(&Bs[row][c4]) = *(const float4*)(B + (size_t)(k0 + row) * F + c4);
        }
        __syncthreads();
#pragma unroll
        for (int kk = 0; kk < 16; kk++) {
            float ra[8], rb[8];
            *(float4*)(ra)     = *(const float4*)(&As[kk][ty * 8]);
            *(float4*)(ra + 4) = *(const float4*)(&As[kk][ty * 8 + 4]);
            *(float4*)(rb)     = *(const float4*)(&Bs[kk][tx * 8]);
            *(float4*)(rb + 4) = *(const float4*)(&Bs[kk][tx * 8 + 4]);
#pragma unroll
            for (int r = 0; r < 8; r++)
#pragma unroll
                for (int c = 0; c < 8; c++) acc[r][c] += ra[r] * rb[c];
        }
        __syncthreads();
    }
#pragma unroll
    for (int r = 0; r < 8; r++) {
        int gr = r0 + ty * 8 + r;
        if (gr < nrows) {
            float o[8];
#pragma unroll
            for (int c = 0; c < 8; c++) {
                float v = acc[r][c];
                if (bias) v += bias[tx * 8 + c];
                if (relu) v = fmaxf(v, 0.f);
                o[c] = v;
            }
            *(float4*)(g_xl + (size_t)gr * F + tx * 8)     = *(float4*)(o);
            *(float4*)(g_xl + (size_t)gr * F + tx * 8 + 4) = *(float4*)(o + 4);
        }
    }
}

// ---------------- per-node attention scalars: as = xl·a_s, ad = xl·a_d, self alpha ----------------
__global__ void k_dots(const float* __restrict__ a_s, const float* __restrict__ a_d,
                       int layer, int n) {
    int g = blockIdx.x * blockDim.x + threadIdx.x;
    int node = g >> 5;
    int lane = g & 31;
    if (node >= n) return;
    float4 x = *(const float4*)(g_xl + (size_t)node * F + lane * 4);
    float4 s4 = *(const float4*)(a_s + lane * 4);
    float4 d4 = *(const float4*)(a_d + lane * 4);
    float ps = x.x * s4.x + x.y * s4.y + x.z * s4.z + x.w * s4.w;
    float pd = x.x * d4.x + x.y * d4.y + x.z * d4.z + x.w * d4.w;
#pragma unroll
    for (int o = 16; o; o >>= 1) {
        ps += __shfl_xor_sync(0xffffffffu, ps, o);
        pd += __shfl_xor_sync(0xffffffffu, pd, o);
    }
    if (lane == 0) {
        g_as[node] = ps;
        g_ad[node] = pd;
        float aeL = layer ? g_aeL1[node] : g_aeL0[node];
        float a = ps + pd + aeL;
        g_alphaSelf[node] = a > 0.f ? a : SLOPE * a;
    }
}

// ---------------- warp-per-node online-softmax aggregation (single pass) ----------------
__global__ void k_agg(const float* __restrict__ bias, int layer, int n) {
    int gw = (blockIdx.x * blockDim.x + threadIdx.x) >> 5;   // node = global warp id
    int lane = threadIdx.x & 31;
    if (gw >= n) return;
    const float* __restrict__ ae = layer ? g_csr_ae1 : g_csr_ae0;
    int s0 = g_off[gw], e0 = g_off[gw + 1];
    float adv = g_ad[gw];
    float aself = g_alphaSelf[gw];

    float m = aself;       // running max
    float ssum = 1.0f;     // exp(aself - m) = 1
    float4 acc = *(const float4*)(g_xl + (size_t)gw * F + lane * 4);  // self row, weight 1

    for (int base = s0; base < e0; base += 32) {
        int i = base + lane;
        float a = -3.4e38f;
        int u = 0;
        if (i < e0) {
            u = g_csr_src[i];
            a = g_as[u] + adv + ae[i];
            a = a > 0.f ? a : SLOPE * a;
        }
        // chunk max
        float cm = a;
#pragma unroll
        for (int o = 16; o; o >>= 1) cm = fmaxf(cm, __shfl_xor_sync(0xffffffffu, cm, o));
        if (cm > m) {
            float sc = __expf(m - cm);
            ssum *= sc;
            acc.x *= sc; acc.y *= sc; acc.z *= sc; acc.w *= sc;
            m = cm;
        }
        float ex = (i < e0) ? __expf(a - m) : 0.f;
        float es = ex;
#pragma unroll
        for (int o = 16; o; o >>= 1) es += __shfl_xor_sync(0xffffffffu, es, o);
        ssum += es;
        int cnt = min(32, e0 - base);
        for (int j = 0; j < cnt; j++) {
            float wt = __shfl_sync(0xffffffffu, ex, j);
            int uj = __shfl_sync(0xffffffffu, u, j);
            float4 r = *(const float4*)(g_xl + (size_t)uj * F + lane * 4);
            acc.x += wt * r.x; acc.y += wt * r.y;
            acc.z += wt * r.z; acc.w += wt * r.w;
        }
    }
    float rinv = 1.0f / ssum;
    float4 b4 = *(const float4*)(bias + lane * 4);
    float4 o;
    o.x = fmaxf(acc.x * rinv + b4.x, 0.f);
    o.y = fmaxf(acc.y * rinv + b4.y, 0.f);
    o.z = fmaxf(acc.z * rinv + b4.z, 0.f);
    o.w = fmaxf(acc.w * rinv + b4.w, 0.f);
    *(float4*)(g_buf + (size_t)gw * F + lane * 4) = o;
}

// ---------------- head: logits = p @ W2 + b2; log_softmax over 16 classes ----------------
__global__ void k_head(const float* __restrict__ W2, const float* __restrict__ b2,
                       float* __restrict__ out, int n) {
    __shared__ float sW[F * NCLS];
    int tid = threadIdx.x;  // 256
    for (int i = tid; i < F * NCLS; i += 256) sW[i] = W2[i];
    __syncthreads();
    int r = tid >> 4, c = tid & 15;
    int node = blockIdx.x * 16 + r;
    bool valid = node < n;
    int nc = valid ? node : (n - 1);
    const float* pr = g_xl + (size_t)nc * F;
    float acc = b2[c];
#pragma unroll 8
    for (int k = 0; k < F; k++) acc += pr[k] * sW[k * NCLS + c];
    float mm = acc;
#pragma unroll
    for (int o = 8; o; o >>= 1) mm = fmaxf(mm, __shfl_xor_sync(0xffffffffu, mm, o));
    float ex = __expf(acc - mm);
    float ssum = ex;
#pragma unroll
    for (int o = 8; o; o >>= 1) ssum += __shfl_xor_sync(0xffffffffu, ssum, o);
    if (valid) out[(size_t)node * NCLS + c] = acc - mm - logf(ssum);
}

// ---------------- driver ----------------
extern "C" void kernel_launch(void* const* d_in, const int* in_sizes, int n_in,
                              void* d_out, int out_size) {
    const float* x      = (const float*)d_in[0];
    const float* ea     = (const float*)d_in[1];
    const float* W0     = (const float*)d_in[2];
    const float* a_src0 = (const float*)d_in[3];
    const float* a_dst0 = (const float*)d_in[4];
    const float* We0    = (const float*)d_in[5];
    const float* a_e0   = (const float*)d_in[6];
    const float* b0     = (const float*)d_in[7];
    const float* W1     = (const float*)d_in[8];
    const float* a_src1 = (const float*)d_in[9];
    const float* a_dst1 = (const float*)d_in[10];
    const float* We1    = (const float*)d_in[11];
    const float* a_e1   = (const float*)d_in[12];
    const float* b1     = (const float*)d_in[13];
    const float* lin1_w = (const float*)d_in[14];
    const float* lin1_b = (const float*)d_in[15];
    const float* lin2_w = (const float*)d_in[16];
    const float* lin2_b = (const float*)d_in[17];
    const int*   ei     = (const int*)d_in[18];   // JAX x64 disabled -> int32

    int n = in_sizes[0] / F;
    int e = in_sizes[1] / EDIM;
    int nb = cdiv(n, SB);
    float* out = (float*)d_out;

    // preprocessing (edge attention scalars + CSR), shared by both layers
    k_we<<<1, 32>>>(We0, a_e0, We1, a_e1);
    k_zero<<<cdiv(n, 256), 256>>>(n);
    k_edge_pre<<<cdiv(e, 256), 256>>>(ea, ei, e);
    k_node_pre<<<cdiv(n, 256), 256>>>(n);
    k_scan1<<<nb, SB>>>(n);
    k_scan2<<<1, 1024>>>(nb);
    k_scan3<<<nb, SB>>>(n);
    k_csr_fill<<<cdiv(e, 256), 256>>>(ei, e);

    // GAT layer 0
    k_gemm<<<cdiv(n, 64), 128>>>(x, W0, nullptr, n, 0);
    k_dots<<<cdiv(n * 32, 256), 256>>>(a_src0, a_dst0, 0, n);
    k_agg<<<cdiv(n, 8), 256>>>(b0, 0, n);

    // GAT layer 1
    k_gemm<<<cdiv(n, 64), 128>>>(nullptr, W1, nullptr, n, 0);
    k_dots<<<cdiv(n * 32, 256), 256>>>(a_src1, a_dst1, 1, n);
    k_agg<<<cdiv(n, 8), 256>>>(b1, 1, n);

    // MLP head
    k_gemm<<<cdiv(n, 64), 128>>>(nullptr, lin1_w, lin1_b, n, 1);
    k_head<<<cdiv(n, 16), 256>>>(lin2_w, lin2_b, out, n);
}

// round 5
// speedup vs baseline: 2.3491x; 1.4473x over previous
#include <cuda_runtime.h>
#include <cstdint>

#define NN 100000
#define NE 1600000
#define F 128
#define EDIM 16
#define NCLS 16
#define SLOPE 0.2f
#define SB 512

// ---------------- scratch (device globals; no allocation allowed) ----------------
__device__ __align__(16) float g_xl[(size_t)NN * F];
__device__ __align__(16) float g_buf[(size_t)NN * F];
__device__ float g_as[NN];
__device__ float g_ad[NN];
__device__ float g_alphaSelf[NN];
__device__ float g_ae0[NE];
__device__ float g_ae1[NE];
__device__ float g_sum0[NN];
__device__ float g_sum1[NN];
__device__ int   g_degi[NN];
__device__ float g_aeL0[NN];
__device__ float g_aeL1[NN];
__device__ int   g_off[NN + 1];
__device__ int   g_cursor[NN];
__device__ int   g_csr_src[NE];
__device__ float g_csr_ae0[NE];
__device__ float g_csr_ae1[NE];
__device__ int   g_bsum[1024];
__device__ __align__(16) float g_we0[EDIM];
__device__ __align__(16) float g_we1[EDIM];

static inline int cdiv(int a, int b) { return (a + b - 1) / b; }

// ---------------- w_e = We @ a_e ----------------
__global__ void k_we(const float* __restrict__ We0, const float* __restrict__ ae0v,
                     const float* __restrict__ We1, const float* __restrict__ ae1v) {
    int t = threadIdx.x;
    if (t < EDIM) {
        float s = 0.f;
        for (int k = 0; k < F; k++) s += We0[t * F + k] * ae0v[k];
        g_we0[t] = s;
    } else if (t < 2 * EDIM) {
        int j = t - EDIM;
        float s = 0.f;
        for (int k = 0; k < F; k++) s += We1[j * F + k] * ae1v[k];
        g_we1[j] = s;
    }
}

__global__ void k_zero(int n) {
    int i = blockIdx.x * blockDim.x + threadIdx.x;
    if (i < n) { g_sum0[i] = 0.f; g_sum1[i] = 0.f; g_degi[i] = 0; }
}

__global__ void k_edge_pre(const float* __restrict__ ea, const int* __restrict__ ei, int e) {
    int i = blockIdx.x * blockDim.x + threadIdx.x;
    if (i >= e) return;
    int dst = ei[e + i];
    const float4* v = (const float4*)(ea + (size_t)i * EDIM);
    const float4* w0 = (const float4*)g_we0;
    const float4* w1 = (const float4*)g_we1;
    float a0 = 0.f, a1 = 0.f;
#pragma unroll
    for (int q = 0; q < 4; q++) {
        float4 t = v[q];
        float4 u0 = w0[q], u1 = w1[q];
        a0 += t.x * u0.x + t.y * u0.y + t.z * u0.z + t.w * u0.w;
        a1 += t.x * u1.x + t.y * u1.y + t.z * u1.z + t.w * u1.w;
    }
    g_ae0[i] = a0;
    g_ae1[i] = a1;
    atomicAdd(&g_sum0[dst], a0);
    atomicAdd(&g_sum1[dst], a1);
    atomicAdd(&g_degi[dst], 1);
}

__global__ void k_node_pre(int n) {
    int i = blockIdx.x * blockDim.x + threadIdx.x;
    if (i >= n) return;
    float d = (float)(g_degi[i] > 0 ? g_degi[i] : 1);
    g_aeL0[i] = g_sum0[i] / d;
    g_aeL1[i] = g_sum1[i] / d;
}

// ---------------- multi-block scan ----------------
__global__ void k_scan1(int n) {
    __shared__ int wsum[16];
    int tid = threadIdx.x;
    int i = blockIdx.x * SB + tid;
    int lane = tid & 31, wid = tid >> 5;
    int v = (i < n) ? g_degi[i] : 0;
    int x = v;
#pragma unroll
    for (int d = 1; d < 32; d <<= 1) {
        int y = __shfl_up_sync(0xffffffffu, x, d);
        if (lane >= d) x += y;
    }
    if (lane == 31) wsum[wid] = x;
    __syncthreads();
    if (tid < 16) {
        int w = wsum[tid];
#pragma unroll
        for (int d = 1; d < 16; d <<= 1) {
            int y = __shfl_up_sync(0x0000ffffu, w, d);
            if (tid >= d) w += y;
        }
        wsum[tid] = w;
    }
    __syncthreads();
    int excl = (wid ? wsum[wid - 1] : 0) + x - v;
    if (i < n) g_off[i] = excl;
    if (tid == SB - 1) g_bsum[blockIdx.x] = wsum[15];
}

__global__ void k_scan2(int nb) {
    __shared__ int wsum[32];
    int tid = threadIdx.x;
    int lane = tid & 31, wid = tid >> 5;
    int v = (tid < nb) ? g_bsum[tid] : 0;
    int x = v;
#pragma unroll
    for (int d = 1; d < 32; d <<= 1) {
        int y = __shfl_up_sync(0xffffffffu, x, d);
        if (lane >= d) x += y;
    }
    if (lane == 31) wsum[wid] = x;
    __syncthreads();
    if (tid < 32) {
        int w = wsum[tid];
#pragma unroll
        for (int d = 1; d < 32; d <<= 1) {
            int y = __shfl_up_sync(0xffffffffu, w, d);
            if (tid >= d) w += y;
        }
        wsum[tid] = w;
    }
    __syncthreads();
    int excl = (wid ? wsum[wid - 1] : 0) + x - v;
    if (tid < nb) g_bsum[tid] = excl;
}

__global__ void k_scan3(int n) {
    int i = blockIdx.x * SB + threadIdx.x;
    if (i >= n) return;
    int o = g_off[i] + g_bsum[i / SB];
    g_off[i] = o;
    g_cursor[i] = o;
    if (i == n - 1) g_off[n] = o + g_degi[i];
}

__global__ void k_csr_fill(const int* __restrict__ ei, int e) {
    int i = blockIdx.x * blockDim.x + threadIdx.x;
    if (i >= e) return;
    int src = ei[i];
    int dst = ei[e + i];
    int pos = atomicAdd(&g_cursor[dst], 1);
    g_csr_src[pos] = src;
    g_csr_ae0[pos] = g_ae0[i];
    g_csr_ae1[pos] = g_ae1[i];
}

// ======== tf32 mma.sync GEMM: C[n,128] = A[n,128] @ W[128,128] (+bias, relu) ========
// 256 threads (8 warps), tile M=128 N=128, K chunks of 32.
// Warp tile 32x64: warp_m = wid&3, warp_n = wid>>2. m16n8k8 fragments.
__device__ __forceinline__ uint32_t f2tf(float f) {
    uint32_t r;
    asm("cvt.rna.tf32.f32 %0, %1;" : "=r"(r) : "f"(f));
    return r;
}
__device__ __forceinline__ void mma8(float* c, const uint32_t* a, const uint32_t* b) {
    asm volatile(
        "mma.sync.aligned.m16n8k8.row.col.f32.tf32.tf32.f32 "
        "{%0,%1,%2,%3},{%4,%5,%6,%7},{%8,%9},{%0,%1,%2,%3};"
        : "+f"(c[0]), "+f"(c[1]), "+f"(c[2]), "+f"(c[3])
        : "r"(a[0]), "r"(a[1]), "r"(a[2]), "r"(a[3]), "r"(b[0]), "r"(b[1]));
}

__global__ void __launch_bounds__(256) k_gemm_mma(
    const float* __restrict__ A_in, const float* __restrict__ Bw,
    const float* __restrict__ bias, int nrows, int relu) {
    const float* A = A_in ? A_in : g_buf;
    __shared__ uint32_t As[128][36];   // [m][k], pad 36 -> conflict-free frag loads
    __shared__ uint32_t Bs[32][136];   // [k][n], pad 136
    int tid = threadIdx.x;
    int lane = tid & 31, wid = tid >> 5;
    int wm = wid & 3, wn = wid >> 2;
    int r0 = blockIdx.x * 128;
    int gid = lane >> 2, tig = lane & 3;

    float acc[2][8][4];
#pragma unroll
    for (int mt = 0; mt < 2; mt++)
#pragma unroll
        for (int nt = 0; nt < 8; nt++)
#pragma unroll
            for (int q = 0; q < 4; q++) acc[mt][nt][q] = 0.f;

    for (int kc = 0; kc < 128; kc += 32) {
        // A tile 128x32
#pragma unroll
        for (int it = 0; it < 4; it++) {
            int f = tid + it * 256;          // float4 idx, 1024 total
            int row = f >> 3;
            int col = (f & 7) * 4;
            int gr = r0 + row;
            if (gr >= nrows) gr = nrows - 1;
            float4 v = *(const float4*)(A + (size_t)gr * F + kc + col);
            As[row][col + 0] = f2tf(v.x);
            As[row][col + 1] = f2tf(v.y);
            As[row][col + 2] = f2tf(v.z);
            As[row][col + 3] = f2tf(v.w);
        }
        // B tile 32x128 (W rows kc..kc+31)
#pragma unroll
        for (int it = 0; it < 4; it++) {
            int f = tid + it * 256;
            int k = f >> 5;
            int c = (f & 31) * 4;
            float4 v = *(const float4*)(Bw + (size_t)(kc + k) * F + c);
            Bs[k][c + 0] = f2tf(v.x);
            Bs[k][c + 1] = f2tf(v.y);
            Bs[k][c + 2] = f2tf(v.z);
            Bs[k][c + 3] = f2tf(v.w);
        }
        __syncthreads();
#pragma unroll
        for (int ks = 0; ks < 4; ks++) {
            int kb = ks * 8;
            uint32_t a[2][4], b[8][2];
#pragma unroll
            for (int mt = 0; mt < 2; mt++) {
                int m = wm * 32 + mt * 16 + gid;
                a[mt][0] = As[m][kb + tig];
                a[mt][1] = As[m + 8][kb + tig];
                a[mt][2] = As[m][kb + tig + 4];
                a[mt][3] = As[m + 8][kb + tig + 4];
            }
#pragma unroll
            for (int nt = 0; nt < 8; nt++) {
                int n = wn * 64 + nt * 8 + gid;
                b[nt][0] = Bs[kb + tig][n];
                b[nt][1] = Bs[kb + tig + 4][n];
            }
#pragma unroll
            for (int mt = 0; mt < 2; mt++)
#pragma unroll
                for (int nt = 0; nt < 8; nt++)
                    mma8(acc[mt][nt], a[mt], b[nt]);
        }
        __syncthreads();
    }
    // epilogue: c0/c1 -> (row, col..col+1), c2/c3 -> (row+8, col..col+1)
#pragma unroll
    for (int mt = 0; mt < 2; mt++) {
        int gr = r0 + wm * 32 + mt * 16 + gid;
#pragma unroll
        for (int nt = 0; nt < 8; nt++) {
            int gc = wn * 64 + nt * 8 + 2 * tig;
            float b0 = bias ? bias[gc] : 0.f;
            float b1 = bias ? bias[gc + 1] : 0.f;
            if (gr < nrows) {
                float2 o;
                o.x = acc[mt][nt][0] + b0;
                o.y = acc[mt][nt][1] + b1;
                if (relu) { o.x = fmaxf(o.x, 0.f); o.y = fmaxf(o.y, 0.f); }
                *(float2*)(g_xl + (size_t)gr * F + gc) = o;
            }
            if (gr + 8 < nrows) {
                float2 o;
                o.x = acc[mt][nt][2] + b0;
                o.y = acc[mt][nt][3] + b1;
                if (relu) { o.x = fmaxf(o.x, 0.f); o.y = fmaxf(o.y, 0.f); }
                *(float2*)(g_xl + (size_t)(gr + 8) * F + gc) = o;
            }
        }
    }
}

// ---------------- per-node attention scalars ----------------
__global__ void k_dots(const float* __restrict__ a_s, const float* __restrict__ a_d,
                       int layer, int n) {
    int g = blockIdx.x * blockDim.x + threadIdx.x;
    int node = g >> 5;
    int lane = g & 31;
    if (node >= n) return;
    float4 x = *(const float4*)(g_xl + (size_t)node * F + lane * 4);
    float4 s4 = *(const float4*)(a_s + lane * 4);
    float4 d4 = *(const float4*)(a_d + lane * 4);
    float ps = x.x * s4.x + x.y * s4.y + x.z * s4.z + x.w * s4.w;
    float pd = x.x * d4.x + x.y * d4.y + x.z * d4.z + x.w * d4.w;
#pragma unroll
    for (int o = 16; o; o >>= 1) {
        ps += __shfl_xor_sync(0xffffffffu, ps, o);
        pd += __shfl_xor_sync(0xffffffffu, pd, o);
    }
    if (lane == 0) {
        g_as[node] = ps;
        g_ad[node] = pd;
        float aeL = layer ? g_aeL1[node] : g_aeL0[node];
        float a = ps + pd + aeL;
        g_alphaSelf[node] = a > 0.f ? a : SLOPE * a;
    }
}

// ---------------- warp-per-node online-softmax aggregation ----------------
__global__ void k_agg(const float* __restrict__ bias, int layer, int n) {
    int gw = (blockIdx.x * blockDim.x + threadIdx.x) >> 5;
    int lane = threadIdx.x & 31;
    if (gw >= n) return;
    const float* __restrict__ ae = layer ? g_csr_ae1 : g_csr_ae0;
    int s0 = g_off[gw], e0 = g_off[gw + 1];
    float adv = g_ad[gw];
    float aself = g_alphaSelf[gw];

    float m = aself;
    float ssum = 1.0f;
    float4 acc = *(const float4*)(g_xl + (size_t)gw * F + lane * 4);

    for (int base = s0; base < e0; base += 32) {
        int i = base + lane;
        float a = -3.4e38f;
        int u = 0;
        if (i < e0) {
            u = g_csr_src[i];
            a = g_as[u] + adv + ae[i];
            a = a > 0.f ? a : SLOPE * a;
        }
        float cm = a;
#pragma unroll
        for (int o = 16; o; o >>= 1) cm = fmaxf(cm, __shfl_xor_sync(0xffffffffu, cm, o));
        if (cm > m) {
            float sc = __expf(m - cm);
            ssum *= sc;
            acc.x *= sc; acc.y *= sc; acc.z *= sc; acc.w *= sc;
            m = cm;
        }
        float ex = (i < e0) ? __expf(a - m) : 0.f;
        float es = ex;
#pragma unroll
        for (int o = 16; o; o >>= 1) es += __shfl_xor_sync(0xffffffffu, es, o);
        ssum += es;
        int cnt = min(32, e0 - base);
        for (int j = 0; j < cnt; j++) {
            float wt = __shfl_sync(0xffffffffu, ex, j);
            int uj = __shfl_sync(0xffffffffu, u, j);
            float4 r = *(const float4*)(g_xl + (size_t)uj * F + lane * 4);
            acc.x += wt * r.x; acc.y += wt * r.y;
            acc.z += wt * r.z; acc.w += wt * r.w;
        }
    }
    float rinv = 1.0f / ssum;
    float4 b4 = *(const float4*)(bias + lane * 4);
    float4 o;
    o.x = fmaxf(acc.x * rinv + b4.x, 0.f);
    o.y = fmaxf(acc.y * rinv + b4.y, 0.f);
    o.z = fmaxf(acc.z * rinv + b4.z, 0.f);
    o.w = fmaxf(acc.w * rinv + b4.w, 0.f);
    *(float4*)(g_buf + (size_t)gw * F + lane * 4) = o;
}

// ---------------- head ----------------
__global__ void k_head(const float* __restrict__ W2, const float* __restrict__ b2,
                       float* __restrict__ out, int n) {
    __shared__ float sW[F * NCLS];
    int tid = threadIdx.x;
    for (int i = tid; i < F * NCLS; i += 256) sW[i] = W2[i];
    __syncthreads();
    int r = tid >> 4, c = tid & 15;
    int node = blockIdx.x * 16 + r;
    bool valid = node < n;
    int nc = valid ? node : (n - 1);
    const float* pr = g_xl + (size_t)nc * F;
    float acc = b2[c];
#pragma unroll 8
    for (int k = 0; k < F; k++) acc += pr[k] * sW[k * NCLS + c];
    float mm = acc;
#pragma unroll
    for (int o = 8; o; o >>= 1) mm = fmaxf(mm, __shfl_xor_sync(0xffffffffu, mm, o));
    float ex = __expf(acc - mm);
    float ssum = ex;
#pragma unroll
    for (int o = 8; o; o >>= 1) ssum += __shfl_xor_sync(0xffffffffu, ssum, o);
    if (valid) out[(size_t)node * NCLS + c] = acc - mm - logf(ssum);
}

// ---------------- driver ----------------
extern "C" void kernel_launch(void* const* d_in, const int* in_sizes, int n_in,
                              void* d_out, int out_size) {
    const float* x      = (const float*)d_in[0];
    const float* ea     = (const float*)d_in[1];
    const float* W0     = (const float*)d_in[2];
    const float* a_src0 = (const float*)d_in[3];
    const float* a_dst0 = (const float*)d_in[4];
    const float* We0    = (const float*)d_in[5];
    const float* a_e0   = (const float*)d_in[6];
    const float* b0     = (const float*)d_in[7];
    const float* W1     = (const float*)d_in[8];
    const float* a_src1 = (const float*)d_in[9];
    const float* a_dst1 = (const float*)d_in[10];
    const float* We1    = (const float*)d_in[11];
    const float* a_e1   = (const float*)d_in[12];
    const float* b1     = (const float*)d_in[13];
    const float* lin1_w = (const float*)d_in[14];
    const float* lin1_b = (const float*)d_in[15];
    const float* lin2_w = (const float*)d_in[16];
    const float* lin2_b = (const float*)d_in[17];
    const int*   ei     = (const int*)d_in[18];

    int n = in_sizes[0] / F;
    int e = in_sizes[1] / EDIM;
    int nb = cdiv(n, SB);
    float* out = (float*)d_out;

    k_we<<<1, 32>>>(We0, a_e0, We1, a_e1);
    k_zero<<<cdiv(n, 256), 256>>>(n);
    k_edge_pre<<<cdiv(e, 256), 256>>>(ea, ei, e);
    k_node_pre<<<cdiv(n, 256), 256>>>(n);
    k_scan1<<<nb, SB>>>(n);
    k_scan2<<<1, 1024>>>(nb);
    k_scan3<<<nb, SB>>>(n);
    k_csr_fill<<<cdiv(e, 256), 256>>>(ei, e);

    // GAT layer 0
    k_gemm_mma<<<cdiv(n, 128), 256>>>(x, W0, nullptr, n, 0);
    k_dots<<<cdiv(n * 32, 256), 256>>>(a_src0, a_dst0, 0, n);
    k_agg<<<cdiv(n, 8), 256>>>(b0, 0, n);

    // GAT layer 1
    k_gemm_mma<<<cdiv(n, 128), 256>>>(nullptr, W1, nullptr, n, 0);
    k_dots<<<cdiv(n * 32, 256), 256>>>(a_src1, a_dst1, 1, n);
    k_agg<<<cdiv(n, 8), 256>>>(b1, 1, n);

    // MLP head
    k_gemm_mma<<<cdiv(n, 128), 256>>>(nullptr, lin1_w, lin1_b, n, 1);
    k_head<<<cdiv(n, 16), 256>>>(lin2_w, lin2_b, out, n);
}